// round 1
// baseline (speedup 1.0000x reference)
#include <cuda_runtime.h>
#include <cuda_bf16.h>
#include <cstdint>

// Problem constants
#define BATCH 128
#define SEQ   256
#define EMB   1024
#define HEADS 16
#define HDIM  64
#define MTOT  (BATCH * SEQ)        // 32768
#define NQKV  (3 * EMB)            // 3072
#define BIAS_ROWS 961              // (2*16-1)^2

// Scratch buffers (allocation-free rule: __device__ globals)
__device__ float g_qkv[(size_t)MTOT * NQKV];   // [32768, 3072]  q|k|v per token
__device__ float g_ctx[(size_t)MTOT * EMB];    // [32768, 1024]

// ---------------------------------------------------------------------------
// SGEMM (TN): C[m,n] = sum_k A[m,k] * B[n,k] + bias[n]
// A: [M,K] row-major, B: [N,K] row-major (both K-contiguous)
// 128x128 block, 8x8 per thread, BK=8, double-buffered smem.
// ---------------------------------------------------------------------------
__global__ __launch_bounds__(256, 2) void sgemm_tn_bias(
    const float* __restrict__ A, const float* __restrict__ B,
    const float* __restrict__ bias, float* __restrict__ C,
    int M, int N, int K)
{
    __shared__ float As[2][8][128];
    __shared__ float Bs[2][8][128];

    const int tid = threadIdx.x;
    const int bm = blockIdx.y * 128;
    const int bn = blockIdx.x * 128;

    // Global->smem loading: 256 threads cover 128 rows x 8 k (one float4 each)
    const int lr = tid >> 1;             // row 0..127
    const int lk = (tid & 1) << 2;       // k offset 0 or 4
    const float* Ap = A + (size_t)(bm + lr) * K + lk;
    const float* Bp = B + (size_t)(bn + lr) * K + lk;

    // Compute mapping: 16x16 thread grid, 8x8 micro-tile
    const int tx = (tid & 15) << 3;      // 0..120
    const int ty = (tid >> 4) << 3;      // 0..120

    float acc[8][8];
#pragma unroll
    for (int i = 0; i < 8; i++)
#pragma unroll
        for (int j = 0; j < 8; j++) acc[i][j] = 0.f;

    // Prologue: stage 0
    float4 a4 = *(const float4*)Ap;
    float4 b4 = *(const float4*)Bp;
    As[0][lk + 0][lr] = a4.x; As[0][lk + 1][lr] = a4.y;
    As[0][lk + 2][lr] = a4.z; As[0][lk + 3][lr] = a4.w;
    Bs[0][lk + 0][lr] = b4.x; Bs[0][lk + 1][lr] = b4.y;
    Bs[0][lk + 2][lr] = b4.z; Bs[0][lk + 3][lr] = b4.w;
    __syncthreads();

    int buf = 0;
    for (int k0 = 8; k0 < K + 8; k0 += 8) {
        const bool has_next = (k0 < K);
        if (has_next) {
            a4 = *(const float4*)(Ap + k0);
            b4 = *(const float4*)(Bp + k0);
        }
#pragma unroll
        for (int k = 0; k < 8; k++) {
            float4 a0 = *(const float4*)&As[buf][k][ty];
            float4 a1 = *(const float4*)&As[buf][k][ty + 4];
            float4 b0 = *(const float4*)&Bs[buf][k][tx];
            float4 b1 = *(const float4*)&Bs[buf][k][tx + 4];
            float ar[8] = {a0.x, a0.y, a0.z, a0.w, a1.x, a1.y, a1.z, a1.w};
            float br[8] = {b0.x, b0.y, b0.z, b0.w, b1.x, b1.y, b1.z, b1.w};
#pragma unroll
            for (int i = 0; i < 8; i++)
#pragma unroll
                for (int j = 0; j < 8; j++)
                    acc[i][j] = fmaf(ar[i], br[j], acc[i][j]);
        }
        if (has_next) {
            buf ^= 1;
            As[buf][lk + 0][lr] = a4.x; As[buf][lk + 1][lr] = a4.y;
            As[buf][lk + 2][lr] = a4.z; As[buf][lk + 3][lr] = a4.w;
            Bs[buf][lk + 0][lr] = b4.x; Bs[buf][lk + 1][lr] = b4.y;
            Bs[buf][lk + 2][lr] = b4.z; Bs[buf][lk + 3][lr] = b4.w;
            __syncthreads();
        }
    }

    // Epilogue: add bias, vectorized stores
    float bvals[8];
#pragma unroll
    for (int j = 0; j < 8; j++) bvals[j] = bias[bn + tx + j];
#pragma unroll
    for (int i = 0; i < 8; i++) {
        float* Cp = C + (size_t)(bm + ty + i) * N + bn + tx;
        float4 v0, v1;
        v0.x = acc[i][0] + bvals[0]; v0.y = acc[i][1] + bvals[1];
        v0.z = acc[i][2] + bvals[2]; v0.w = acc[i][3] + bvals[3];
        v1.x = acc[i][4] + bvals[4]; v1.y = acc[i][5] + bvals[5];
        v1.z = acc[i][6] + bvals[6]; v1.w = acc[i][7] + bvals[7];
        *(float4*)(Cp)     = v0;
        *(float4*)(Cp + 4) = v1;
    }
}

// ---------------------------------------------------------------------------
// Window attention: one block per (b, h), one thread per query row.
// Online softmax streaming K/V in 64-row smem tiles.
// scores = (q . k) / 8 + bias_table[rel_index[q,k], h]
// ---------------------------------------------------------------------------
__global__ __launch_bounds__(256) void attn_kernel(
    const float* __restrict__ qkv, const float* __restrict__ bias_table,
    const int* __restrict__ rel_index, float* __restrict__ ctx)
{
    const int bh = blockIdx.x;
    const int b = bh >> 4;        // / HEADS
    const int h = bh & 15;        // % HEADS
    const int tid = threadIdx.x;  // query row 0..255

    __shared__ float ks[64][64];
    __shared__ float vs[64][64];
    __shared__ float bias_col[BIAS_ROWS];

    for (int i = tid; i < BIAS_ROWS; i += 256)
        bias_col[i] = bias_table[i * HEADS + h];

    // Load this thread's q row into registers
    const size_t tok = (size_t)b * SEQ + tid;
    const float* qp = qkv + tok * NQKV + h * HDIM;
    float qreg[HDIM];
#pragma unroll
    for (int d4 = 0; d4 < 16; d4++) {
        float4 v = *(const float4*)(qp + d4 * 4);
        qreg[d4 * 4 + 0] = v.x; qreg[d4 * 4 + 1] = v.y;
        qreg[d4 * 4 + 2] = v.z; qreg[d4 * 4 + 3] = v.w;
    }

    float m = -1e30f, l = 0.f;
    float acc[HDIM];
#pragma unroll
    for (int d = 0; d < HDIM; d++) acc[d] = 0.f;

    const int lrow = tid >> 2;            // 0..63
    const int lcol = (tid & 3) << 4;      // 0,16,32,48
    const float scale = 0.125f;           // 1/sqrt(64)
    const int* relrow = rel_index + (size_t)tid * SEQ;

    for (int kt = 0; kt < 4; kt++) {
        __syncthreads();   // bias_col ready (iter 0) / tile reads done (iter>0)
        {
            const size_t kb = ((size_t)b * SEQ + kt * 64 + lrow) * NQKV
                            + (size_t)h * HDIM + EMB + lcol;
#pragma unroll
            for (int c = 0; c < 16; c += 4) {
                *(float4*)&ks[lrow][lcol + c] = *(const float4*)(qkv + kb + c);
                *(float4*)&vs[lrow][lcol + c] = *(const float4*)(qkv + kb + EMB + c);
            }
        }
        __syncthreads();

        for (int kk = 0; kk < 64; kk += 4) {
            const int4 r4 = *(const int4*)(relrow + kt * 64 + kk);
            const int ridx[4] = {r4.x, r4.y, r4.z, r4.w};
#pragma unroll
            for (int u = 0; u < 4; u++) {
                const int krow = kk + u;
                float s0 = 0.f, s1 = 0.f, s2 = 0.f, s3 = 0.f;
#pragma unroll
                for (int d = 0; d < HDIM; d += 4) {
                    s0 = fmaf(qreg[d + 0], ks[krow][d + 0], s0);
                    s1 = fmaf(qreg[d + 1], ks[krow][d + 1], s1);
                    s2 = fmaf(qreg[d + 2], ks[krow][d + 2], s2);
                    s3 = fmaf(qreg[d + 3], ks[krow][d + 3], s3);
                }
                float s = (s0 + s1) + (s2 + s3);
                s = fmaf(s, scale, bias_col[ridx[u]]);
                if (s <= m) {
                    const float p = exp2f((s - m) * 1.44269504f);
                    l += p;
#pragma unroll
                    for (int d = 0; d < HDIM; d++)
                        acc[d] = fmaf(p, vs[krow][d], acc[d]);
                } else {
                    const float corr = exp2f((m - s) * 1.44269504f);
                    l = fmaf(l, corr, 1.0f);
#pragma unroll
                    for (int d = 0; d < HDIM; d++)
                        acc[d] = fmaf(acc[d], corr, vs[krow][d]);
                    m = s;
                }
            }
        }
    }

    const float inv = 1.0f / l;
    float* op = ctx + tok * EMB + h * HDIM;
#pragma unroll
    for (int d4 = 0; d4 < 16; d4++) {
        float4 v;
        v.x = acc[d4 * 4 + 0] * inv; v.y = acc[d4 * 4 + 1] * inv;
        v.z = acc[d4 * 4 + 2] * inv; v.w = acc[d4 * 4 + 3] * inv;
        *(float4*)(op + d4 * 4) = v;
    }
}

// ---------------------------------------------------------------------------
extern "C" void kernel_launch(void* const* d_in, const int* in_sizes, int n_in,
                              void* d_out, int out_size)
{
    const float* x          = (const float*)d_in[0];
    const float* qkv_w      = (const float*)d_in[1];
    const float* qkv_b      = (const float*)d_in[2];
    const float* out_w      = (const float*)d_in[3];
    const float* out_b      = (const float*)d_in[4];
    const float* bias_table = (const float*)d_in[5];
    const int*   rel_index  = (const int*)d_in[6];
    float* out = (float*)d_out;

    float* qkv; float* ctx;
    cudaGetSymbolAddress((void**)&qkv, g_qkv);
    cudaGetSymbolAddress((void**)&ctx, g_ctx);

    // 1) QKV projection: [32768,1024] @ [3072,1024]^T + b
    {
        dim3 grid(NQKV / 128, MTOT / 128);
        sgemm_tn_bias<<<grid, 256>>>(x, qkv_w, qkv_b, qkv, MTOT, NQKV, EMB);
    }
    // 2) Windowed attention with relative-position bias
    attn_kernel<<<BATCH * HEADS, 256>>>(qkv, bias_table, rel_index, ctx);
    // 3) Output projection: [32768,1024] @ [1024,1024]^T + b
    {
        dim3 grid(EMB / 128, MTOT / 128);
        sgemm_tn_bias<<<grid, 256>>>(ctx, out_w, out_b, out, MTOT, EMB, EMB);
    }
}

// round 3
// speedup vs baseline: 1.7712x; 1.7712x over previous
#include <cuda_runtime.h>
#include <cuda_bf16.h>
#include <cstdint>

// Problem constants
#define BATCH 128
#define SEQ   256
#define EMB   1024
#define HEADS 16
#define HDIM  64
#define MTOT  (BATCH * SEQ)        // 32768
#define NQKV  (3 * EMB)            // 3072
#define BIAS_ROWS 961

// GEMM tiling (mma.sync path, portable ISA only)
#define GK      1024
#define BM      128
#define BN      128
#define BKC     32                  // bf16 k per stage
#define KITERS  (GK / BKC)          // 32
#define ROWP    40                  // padded row length (elements) -> 80B stride
#define PLANE_B (128 * ROWP * 2)    // 10240 bytes per plane tile
#define STAGE_B (4 * PLANE_B)       // AH|AL|BH|BL = 40960
#define NSTG    3

// Scratch (__device__ globals; no allocation allowed)
__device__ float g_qkv[(size_t)MTOT * NQKV];             // attention input (fp32)
__device__ __nv_bfloat16 g_xh[(size_t)MTOT * EMB];
__device__ __nv_bfloat16 g_xl[(size_t)MTOT * EMB];
__device__ __nv_bfloat16 g_ch[(size_t)MTOT * EMB];
__device__ __nv_bfloat16 g_cl[(size_t)MTOT * EMB];
__device__ __nv_bfloat16 g_wqh[(size_t)NQKV * EMB];
__device__ __nv_bfloat16 g_wql[(size_t)NQKV * EMB];
__device__ __nv_bfloat16 g_woh[(size_t)EMB * EMB];
__device__ __nv_bfloat16 g_wol[(size_t)EMB * EMB];

// ---------------------------------------------------------------------------
// Helpers (portable PTX only: cp.async, ldmatrix, mma.sync)
// ---------------------------------------------------------------------------
__device__ __forceinline__ uint32_t smem_u32(const void* p) {
    uint32_t a;
    asm("{ .reg .u64 t; cvta.to.shared.u64 t, %1; cvt.u32.u64 %0, t; }"
        : "=r"(a) : "l"(p));
    return a;
}
__device__ __forceinline__ void cp16(uint32_t dst, const void* src) {
    asm volatile("cp.async.cg.shared.global [%0], [%1], 16;" :: "r"(dst), "l"(src));
}
__device__ __forceinline__ void cp_commit() {
    asm volatile("cp.async.commit_group;" ::: "memory");
}
__device__ __forceinline__ void cp_wait1() {
    asm volatile("cp.async.wait_group 1;" ::: "memory");
}
__device__ __forceinline__ void ldsm4(uint32_t* r, uint32_t addr) {
    asm volatile("ldmatrix.sync.aligned.m8n8.x4.shared.b16 {%0,%1,%2,%3}, [%4];"
                 : "=r"(r[0]), "=r"(r[1]), "=r"(r[2]), "=r"(r[3]) : "r"(addr));
}
__device__ __forceinline__ void mma16816(float* c, const uint32_t* a, const uint32_t* b) {
    asm volatile(
        "mma.sync.aligned.m16n8k16.row.col.f32.bf16.bf16.f32 "
        "{%0,%1,%2,%3}, {%4,%5,%6,%7}, {%8,%9}, {%0,%1,%2,%3};"
        : "+f"(c[0]), "+f"(c[1]), "+f"(c[2]), "+f"(c[3])
        : "r"(a[0]), "r"(a[1]), "r"(a[2]), "r"(a[3]), "r"(b[0]), "r"(b[1]));
}

// ---------------------------------------------------------------------------
// Split fp32 -> bf16 hi + bf16 lo planes (grid-stride, float4 granule)
// ---------------------------------------------------------------------------
__global__ void split_kernel(const float* __restrict__ src,
                             __nv_bfloat16* __restrict__ hi,
                             __nv_bfloat16* __restrict__ lo, int n4)
{
    for (int i = blockIdx.x * blockDim.x + threadIdx.x; i < n4;
         i += gridDim.x * blockDim.x) {
        float4 v = ((const float4*)src)[i];
        __nv_bfloat16 h0 = __float2bfloat16(v.x);
        __nv_bfloat16 h1 = __float2bfloat16(v.y);
        __nv_bfloat16 h2 = __float2bfloat16(v.z);
        __nv_bfloat16 h3 = __float2bfloat16(v.w);
        __nv_bfloat16 l0 = __float2bfloat16(v.x - __bfloat162float(h0));
        __nv_bfloat16 l1 = __float2bfloat16(v.y - __bfloat162float(h1));
        __nv_bfloat16 l2 = __float2bfloat16(v.z - __bfloat162float(h2));
        __nv_bfloat16 l3 = __float2bfloat16(v.w - __bfloat162float(h3));
        uint2 hp, lp;
        hp.x = ((uint32_t)__bfloat16_as_ushort(h1) << 16) | __bfloat16_as_ushort(h0);
        hp.y = ((uint32_t)__bfloat16_as_ushort(h3) << 16) | __bfloat16_as_ushort(h2);
        lp.x = ((uint32_t)__bfloat16_as_ushort(l1) << 16) | __bfloat16_as_ushort(l0);
        lp.y = ((uint32_t)__bfloat16_as_ushort(l3) << 16) | __bfloat16_as_ushort(l2);
        ((uint2*)hi)[i] = hp;
        ((uint2*)lo)[i] = lp;
    }
}

// ---------------------------------------------------------------------------
// bf16 split GEMM (TN): C[m,n] = sum_k A[m,k]*B[n,k] + bias[n]
// A,B given as hi/lo bf16 planes, K=1024. mma.sync m16n8k16, 3 products.
// 256 threads: 8 warps, warp tile 64(M) x 32(N).
// ---------------------------------------------------------------------------
__global__ __launch_bounds__(256, 1) void gemm_mma(
    const __nv_bfloat16* __restrict__ Ah, const __nv_bfloat16* __restrict__ Al,
    const __nv_bfloat16* __restrict__ Bh, const __nv_bfloat16* __restrict__ Bl,
    const float* __restrict__ bias, float* __restrict__ C, int N)
{
    extern __shared__ char smem[];
    const int tid  = threadIdx.x;
    const int wid  = tid >> 5;
    const int lane = tid & 31;
    const int wm = wid & 1;            // 0..1 -> 64 rows each
    const int wn = wid >> 1;           // 0..3 -> 32 cols each
    const int bm = blockIdx.y * BM;
    const int bn = blockIdx.x * BN;

    float acc[4][4][4];
#pragma unroll
    for (int i = 0; i < 4; i++)
#pragma unroll
        for (int j = 0; j < 4; j++)
#pragma unroll
            for (int c = 0; c < 4; c++) acc[i][j][c] = 0.f;

    // Per-thread load slots: chunk = it*256 + tid; row = chunk>>2; kc = (chunk&3)*8
    const int r0 = tid >> 2, kc0 = (tid & 3) * 8;          // it = 0
    const int r1 = 64 + r0;                                 // it = 1 (chunk+256)

    auto issue = [&](int s, int k0) {
        char* st = smem + s * STAGE_B;
        const uint32_t d0 = smem_u32(st + (r0 * ROWP + kc0) * 2);
        const uint32_t d1 = smem_u32(st + (r1 * ROWP + kc0) * 2);
        const size_t ga0 = (size_t)(bm + r0) * GK + k0 + kc0;
        const size_t ga1 = (size_t)(bm + r1) * GK + k0 + kc0;
        const size_t gb0 = (size_t)(bn + r0) * GK + k0 + kc0;
        const size_t gb1 = (size_t)(bn + r1) * GK + k0 + kc0;
        cp16(d0,                Ah + ga0);  cp16(d1,                Ah + ga1);
        cp16(d0 + PLANE_B,      Al + ga0);  cp16(d1 + PLANE_B,      Al + ga1);
        cp16(d0 + 2 * PLANE_B,  Bh + gb0);  cp16(d1 + 2 * PLANE_B,  Bh + gb1);
        cp16(d0 + 3 * PLANE_B,  Bl + gb0);  cp16(d1 + 3 * PLANE_B,  Bl + gb1);
    };

    issue(0, 0);  cp_commit();
    issue(1, BKC); cp_commit();

    // ldmatrix per-lane address components
    const int a_row = wm * 64 + (lane & 15);
    const int a_k8  = ((lane >> 4) & 1) * 8;
    const int b_row = wn * 32 + ((lane >> 4) << 3) + (lane & 7);
    const int b_k8  = ((lane >> 3) & 1) * 8;

    for (int kt = 0; kt < KITERS; kt++) {
        cp_wait1();
        __syncthreads();
        if (kt < KITERS - 2) { issue((kt + 2) % NSTG, (kt + 2) * BKC); cp_commit(); }

        char* st = smem + (kt % NSTG) * STAGE_B;
        const uint32_t aH = smem_u32(st);
        const uint32_t aL = aH + PLANE_B;
        const uint32_t bH = aH + 2 * PLANE_B;
        const uint32_t bL = aH + 3 * PLANE_B;

#pragma unroll
        for (int ks = 0; ks < 2; ks++) {
            const int akc = ks * 16 + a_k8;
            const int bkc = ks * 16 + b_k8;
            uint32_t ah[4][4], al[4][4], bh[4][2], bl[4][2];
#pragma unroll
            for (int mf = 0; mf < 4; mf++) {
                const uint32_t off = ((a_row + mf * 16) * ROWP + akc) * 2;
                ldsm4(ah[mf], aH + off);
                ldsm4(al[mf], aL + off);
            }
#pragma unroll
            for (int p = 0; p < 2; p++) {
                const uint32_t off = ((b_row + p * 16) * ROWP + bkc) * 2;
                uint32_t t[4];
                ldsm4(t, bH + off);
                bh[p * 2][0] = t[0]; bh[p * 2][1] = t[1];
                bh[p * 2 + 1][0] = t[2]; bh[p * 2 + 1][1] = t[3];
                ldsm4(t, bL + off);
                bl[p * 2][0] = t[0]; bl[p * 2][1] = t[1];
                bl[p * 2 + 1][0] = t[2]; bl[p * 2 + 1][1] = t[3];
            }
#pragma unroll
            for (int mf = 0; mf < 4; mf++)
#pragma unroll
                for (int nf = 0; nf < 4; nf++) {
                    mma16816(acc[mf][nf], ah[mf], bh[nf]);
                    mma16816(acc[mf][nf], ah[mf], bl[nf]);
                    mma16816(acc[mf][nf], al[mf], bh[nf]);
                }
        }
        __syncthreads();
    }

    // Epilogue: direct stores, bias added
    const int er = lane >> 2;          // 0..7
    const int ec = (lane & 3) * 2;     // 0,2,4,6
#pragma unroll
    for (int mf = 0; mf < 4; mf++) {
        const int m0 = bm + wm * 64 + mf * 16 + er;
#pragma unroll
        for (int nf = 0; nf < 4; nf++) {
            const int n0 = bn + wn * 32 + nf * 8 + ec;
            const float b0 = __ldg(&bias[n0]), b1 = __ldg(&bias[n0 + 1]);
            float2 v0 = make_float2(acc[mf][nf][0] + b0, acc[mf][nf][1] + b1);
            float2 v1 = make_float2(acc[mf][nf][2] + b0, acc[mf][nf][3] + b1);
            *(float2*)(C + (size_t)m0 * N + n0)       = v0;
            *(float2*)(C + (size_t)(m0 + 8) * N + n0) = v1;
        }
    }
}

// ---------------------------------------------------------------------------
// Window attention: one block per (b,h), one thread per query row.
// Epilogue writes ctx as bf16 hi/lo planes for gemm2.
// ---------------------------------------------------------------------------
__global__ __launch_bounds__(256) void attn_kernel(
    const float* __restrict__ qkv, const float* __restrict__ bias_table,
    const int* __restrict__ rel_index,
    __nv_bfloat16* __restrict__ ch, __nv_bfloat16* __restrict__ cl)
{
    const int bh = blockIdx.x;
    const int b = bh >> 4;
    const int h = bh & 15;
    const int tid = threadIdx.x;

    __shared__ float ks[64][64];
    __shared__ float vs[64][64];
    __shared__ float bias_col[BIAS_ROWS];

    for (int i = tid; i < BIAS_ROWS; i += 256)
        bias_col[i] = bias_table[i * HEADS + h];

    const size_t tok = (size_t)b * SEQ + tid;
    const float* qp = qkv + tok * NQKV + h * HDIM;
    float qreg[HDIM];
#pragma unroll
    for (int d4 = 0; d4 < 16; d4++) {
        float4 v = *(const float4*)(qp + d4 * 4);
        qreg[d4 * 4 + 0] = v.x; qreg[d4 * 4 + 1] = v.y;
        qreg[d4 * 4 + 2] = v.z; qreg[d4 * 4 + 3] = v.w;
    }

    float m = -1e30f, l = 0.f;
    float acc[HDIM];
#pragma unroll
    for (int d = 0; d < HDIM; d++) acc[d] = 0.f;

    const int lrow = tid >> 2;
    const int lcol = (tid & 3) << 4;
    const float scale = 0.125f;
    const int* relrow = rel_index + (size_t)tid * SEQ;

    for (int kt = 0; kt < 4; kt++) {
        __syncthreads();
        {
            const size_t kb = ((size_t)b * SEQ + kt * 64 + lrow) * NQKV
                            + (size_t)h * HDIM + EMB + lcol;
#pragma unroll
            for (int c = 0; c < 16; c += 4) {
                *(float4*)&ks[lrow][lcol + c] = *(const float4*)(qkv + kb + c);
                *(float4*)&vs[lrow][lcol + c] = *(const float4*)(qkv + kb + EMB + c);
            }
        }
        __syncthreads();

        for (int kk = 0; kk < 64; kk += 4) {
            const int4 r4 = *(const int4*)(relrow + kt * 64 + kk);
            const int ridx[4] = {r4.x, r4.y, r4.z, r4.w};
#pragma unroll
            for (int u = 0; u < 4; u++) {
                const int krow = kk + u;
                float s0 = 0.f, s1 = 0.f, s2 = 0.f, s3 = 0.f;
#pragma unroll
                for (int d = 0; d < HDIM; d += 4) {
                    s0 = fmaf(qreg[d + 0], ks[krow][d + 0], s0);
                    s1 = fmaf(qreg[d + 1], ks[krow][d + 1], s1);
                    s2 = fmaf(qreg[d + 2], ks[krow][d + 2], s2);
                    s3 = fmaf(qreg[d + 3], ks[krow][d + 3], s3);
                }
                float s = (s0 + s1) + (s2 + s3);
                s = fmaf(s, scale, bias_col[ridx[u]]);
                if (s <= m) {
                    const float p = exp2f((s - m) * 1.44269504f);
                    l += p;
#pragma unroll
                    for (int d = 0; d < HDIM; d++)
                        acc[d] = fmaf(p, vs[krow][d], acc[d]);
                } else {
                    const float corr = exp2f((m - s) * 1.44269504f);
                    l = fmaf(l, corr, 1.0f);
#pragma unroll
                    for (int d = 0; d < HDIM; d++)
                        acc[d] = fmaf(acc[d], corr, vs[krow][d]);
                    m = s;
                }
            }
        }
    }

    const float inv = 1.0f / l;
    const size_t obase = tok * EMB + h * HDIM;
#pragma unroll
    for (int d4 = 0; d4 < 16; d4++) {
        float v0 = acc[d4 * 4 + 0] * inv, v1 = acc[d4 * 4 + 1] * inv;
        float v2 = acc[d4 * 4 + 2] * inv, v3 = acc[d4 * 4 + 3] * inv;
        __nv_bfloat16 h0 = __float2bfloat16(v0), h1 = __float2bfloat16(v1);
        __nv_bfloat16 h2 = __float2bfloat16(v2), h3 = __float2bfloat16(v3);
        __nv_bfloat16 l0 = __float2bfloat16(v0 - __bfloat162float(h0));
        __nv_bfloat16 l1 = __float2bfloat16(v1 - __bfloat162float(h1));
        __nv_bfloat16 l2 = __float2bfloat16(v2 - __bfloat162float(h2));
        __nv_bfloat16 l3 = __float2bfloat16(v3 - __bfloat162float(h3));
        uint2 hp, lp;
        hp.x = ((uint32_t)__bfloat16_as_ushort(h1) << 16) | __bfloat16_as_ushort(h0);
        hp.y = ((uint32_t)__bfloat16_as_ushort(h3) << 16) | __bfloat16_as_ushort(h2);
        lp.x = ((uint32_t)__bfloat16_as_ushort(l1) << 16) | __bfloat16_as_ushort(l0);
        lp.y = ((uint32_t)__bfloat16_as_ushort(l3) << 16) | __bfloat16_as_ushort(l2);
        *(uint2*)(ch + obase + d4 * 4) = hp;
        *(uint2*)(cl + obase + d4 * 4) = lp;
    }
}

// ---------------------------------------------------------------------------
extern "C" void kernel_launch(void* const* d_in, const int* in_sizes, int n_in,
                              void* d_out, int out_size)
{
    const float* x          = (const float*)d_in[0];
    const float* qkv_w      = (const float*)d_in[1];
    const float* qkv_b      = (const float*)d_in[2];
    const float* out_w      = (const float*)d_in[3];
    const float* out_b      = (const float*)d_in[4];
    const float* bias_table = (const float*)d_in[5];
    const int*   rel_index  = (const int*)d_in[6];
    float* out = (float*)d_out;

    float* qkv; __nv_bfloat16 *xh, *xl, *ch, *cl, *wqh, *wql, *woh, *wol;
    cudaGetSymbolAddress((void**)&qkv, g_qkv);
    cudaGetSymbolAddress((void**)&xh, g_xh);
    cudaGetSymbolAddress((void**)&xl, g_xl);
    cudaGetSymbolAddress((void**)&ch, g_ch);
    cudaGetSymbolAddress((void**)&cl, g_cl);
    cudaGetSymbolAddress((void**)&wqh, g_wqh);
    cudaGetSymbolAddress((void**)&wql, g_wql);
    cudaGetSymbolAddress((void**)&woh, g_woh);
    cudaGetSymbolAddress((void**)&wol, g_wol);

    const int smem_bytes = NSTG * STAGE_B;   // 122880
    cudaFuncSetAttribute(gemm_mma, cudaFuncAttributeMaxDynamicSharedMemorySize,
                         smem_bytes);

    // 0) Split fp32 inputs into bf16 hi/lo planes
    split_kernel<<<1184, 256>>>(x,     xh,  xl,  MTOT * EMB / 4);
    split_kernel<<<1184, 256>>>(qkv_w, wqh, wql, NQKV * EMB / 4);
    split_kernel<<<592,  256>>>(out_w, woh, wol, EMB * EMB / 4);

    // 1) QKV projection (tensor cores)
    {
        dim3 grid(NQKV / BN, MTOT / BM);   // (24, 256)
        gemm_mma<<<grid, 256, smem_bytes>>>(xh, xl, wqh, wql, qkv_b, qkv, NQKV);
    }
    // 2) Windowed attention (writes ctx hi/lo planes)
    attn_kernel<<<BATCH * HEADS, 256>>>(qkv, bias_table, rel_index, ch, cl);
    // 3) Output projection (tensor cores)
    {
        dim3 grid(EMB / BN, MTOT / BM);    // (8, 256)
        gemm_mma<<<grid, 256, smem_bytes>>>(ch, cl, woh, wol, out_b, out, EMB);
    }
}

// round 5
// speedup vs baseline: 2.2845x; 1.2898x over previous
#include <cuda_runtime.h>
#include <cuda_bf16.h>
#include <cstdint>

// Problem constants
#define BATCH 128
#define SEQ   256
#define EMB   1024
#define HEADS 16
#define HDIM  64
#define MTOT  (BATCH * SEQ)        // 32768
#define NQKV  (3 * EMB)            // 3072

// GEMM tiling (mma.sync path, portable ISA only)
#define GK      1024
#define BM      128
#define BN      128
#define BKC     32
#define KITERS  (GK / BKC)          // 32
#define ROWP    40                  // gemm smem row pitch (elements)
#define PLANE_B (128 * ROWP * 2)
#define STAGE_B (4 * PLANE_B)
#define NSTG    3

#define ROWP2   72                  // attn smem row pitch (64-elem rows, padded)

// Scratch (__device__ globals; no allocation allowed)
__device__ __nv_bfloat16 g_qkvh[(size_t)MTOT * NQKV];
__device__ __nv_bfloat16 g_qkvl[(size_t)MTOT * NQKV];
__device__ __nv_bfloat16 g_xh[(size_t)MTOT * EMB];
__device__ __nv_bfloat16 g_xl[(size_t)MTOT * EMB];
__device__ __nv_bfloat16 g_ch[(size_t)MTOT * EMB];
__device__ __nv_bfloat16 g_cl[(size_t)MTOT * EMB];
__device__ __nv_bfloat16 g_wqh[(size_t)NQKV * EMB];
__device__ __nv_bfloat16 g_wql[(size_t)NQKV * EMB];
__device__ __nv_bfloat16 g_woh[(size_t)EMB * EMB];
__device__ __nv_bfloat16 g_wol[(size_t)EMB * EMB];
__device__ float g_biasg[(size_t)HEADS * SEQ * SEQ];   // [h][q][k]

// ---------------------------------------------------------------------------
// Helpers (portable PTX only)
// ---------------------------------------------------------------------------
__device__ __forceinline__ uint32_t smem_u32(const void* p) {
    uint32_t a;
    asm("{ .reg .u64 t; cvta.to.shared.u64 t, %1; cvt.u32.u64 %0, t; }"
        : "=r"(a) : "l"(p));
    return a;
}
__device__ __forceinline__ void cp16(uint32_t dst, const void* src) {
    asm volatile("cp.async.cg.shared.global [%0], [%1], 16;" :: "r"(dst), "l"(src));
}
__device__ __forceinline__ void cp_commit() {
    asm volatile("cp.async.commit_group;" ::: "memory");
}
__device__ __forceinline__ void cp_wait1() {
    asm volatile("cp.async.wait_group 1;" ::: "memory");
}
__device__ __forceinline__ void ldsm4(uint32_t* r, uint32_t addr) {
    asm volatile("ldmatrix.sync.aligned.m8n8.x4.shared.b16 {%0,%1,%2,%3}, [%4];"
                 : "=r"(r[0]), "=r"(r[1]), "=r"(r[2]), "=r"(r[3]) : "r"(addr));
}
__device__ __forceinline__ void mma16816(float* c, const uint32_t* a, const uint32_t* b) {
    asm volatile(
        "mma.sync.aligned.m16n8k16.row.col.f32.bf16.bf16.f32 "
        "{%0,%1,%2,%3}, {%4,%5,%6,%7}, {%8,%9}, {%0,%1,%2,%3};"
        : "+f"(c[0]), "+f"(c[1]), "+f"(c[2]), "+f"(c[3])
        : "r"(a[0]), "r"(a[1]), "r"(a[2]), "r"(a[3]), "r"(b[0]), "r"(b[1]));
}
__device__ __forceinline__ float ex2f(float x) {
    float y; asm("ex2.approx.f32 %0, %1;" : "=f"(y) : "f"(x)); return y;
}
__device__ __forceinline__ uint32_t packbf(__nv_bfloat16 a, __nv_bfloat16 b) {
    return ((uint32_t)__bfloat16_as_ushort(b) << 16) | __bfloat16_as_ushort(a);
}
__device__ __forceinline__ void split1(float v, __nv_bfloat16& h, __nv_bfloat16& l) {
    h = __float2bfloat16(v);
    l = __float2bfloat16(v - __bfloat162float(h));
}

// ---------------------------------------------------------------------------
// Split fp32 -> bf16 hi + lo planes
// ---------------------------------------------------------------------------
__global__ void split_kernel(const float* __restrict__ src,
                             __nv_bfloat16* __restrict__ hi,
                             __nv_bfloat16* __restrict__ lo, int n4)
{
    for (int i = blockIdx.x * blockDim.x + threadIdx.x; i < n4;
         i += gridDim.x * blockDim.x) {
        float4 v = ((const float4*)src)[i];
        __nv_bfloat16 h0, h1, h2, h3, l0, l1, l2, l3;
        split1(v.x, h0, l0); split1(v.y, h1, l1);
        split1(v.z, h2, l2); split1(v.w, h3, l3);
        uint2 hp = make_uint2(packbf(h0, h1), packbf(h2, h3));
        uint2 lp = make_uint2(packbf(l0, l1), packbf(l2, l3));
        ((uint2*)hi)[i] = hp;
        ((uint2*)lo)[i] = lp;
    }
}

// Precompute biasg[h][q][k] = bias_table[rel_index[q,k]][h]
__global__ void bias_pre(const float* __restrict__ bt, const int* __restrict__ ri,
                         float* __restrict__ bg)
{
    const int qk = blockIdx.x * 256 + threadIdx.x;   // 0..65535
    const int r = ri[qk];
#pragma unroll
    for (int hh = 0; hh < HEADS; hh++)
        bg[(size_t)hh * (SEQ * SEQ) + qk] = bt[r * HEADS + hh];
}

// ---------------------------------------------------------------------------
// bf16 split GEMM (TN): C = A.Bt + bias; OUTF32=1 -> fp32 C, else hi/lo planes
// ---------------------------------------------------------------------------
template <int OUTF32>
__global__ __launch_bounds__(256, 1) void gemm_mma(
    const __nv_bfloat16* __restrict__ Ah, const __nv_bfloat16* __restrict__ Al,
    const __nv_bfloat16* __restrict__ Bh, const __nv_bfloat16* __restrict__ Bl,
    const float* __restrict__ bias, float* __restrict__ C,
    __nv_bfloat16* __restrict__ CH, __nv_bfloat16* __restrict__ CL, int N)
{
    extern __shared__ char smem[];
    const int tid  = threadIdx.x;
    const int wid  = tid >> 5;
    const int lane = tid & 31;
    const int wm = wid & 1;
    const int wn = wid >> 1;
    const int bm = blockIdx.y * BM;
    const int bn = blockIdx.x * BN;

    float acc[4][4][4];
#pragma unroll
    for (int i = 0; i < 4; i++)
#pragma unroll
        for (int j = 0; j < 4; j++)
#pragma unroll
            for (int c = 0; c < 4; c++) acc[i][j][c] = 0.f;

    const int r0 = tid >> 2, kc0 = (tid & 3) * 8;
    const int r1 = 64 + r0;

    auto issue = [&](int s, int k0) {
        char* st = smem + s * STAGE_B;
        const uint32_t d0 = smem_u32(st + (r0 * ROWP + kc0) * 2);
        const uint32_t d1 = smem_u32(st + (r1 * ROWP + kc0) * 2);
        const size_t ga0 = (size_t)(bm + r0) * GK + k0 + kc0;
        const size_t ga1 = (size_t)(bm + r1) * GK + k0 + kc0;
        const size_t gb0 = (size_t)(bn + r0) * GK + k0 + kc0;
        const size_t gb1 = (size_t)(bn + r1) * GK + k0 + kc0;
        cp16(d0,                Ah + ga0);  cp16(d1,                Ah + ga1);
        cp16(d0 + PLANE_B,      Al + ga0);  cp16(d1 + PLANE_B,      Al + ga1);
        cp16(d0 + 2 * PLANE_B,  Bh + gb0);  cp16(d1 + 2 * PLANE_B,  Bh + gb1);
        cp16(d0 + 3 * PLANE_B,  Bl + gb0);  cp16(d1 + 3 * PLANE_B,  Bl + gb1);
    };

    issue(0, 0);  cp_commit();
    issue(1, BKC); cp_commit();

    const int a_row = wm * 64 + (lane & 15);
    const int a_k8  = ((lane >> 4) & 1) * 8;
    const int b_row = wn * 32 + ((lane >> 4) << 3) + (lane & 7);
    const int b_k8  = ((lane >> 3) & 1) * 8;

    for (int kt = 0; kt < KITERS; kt++) {
        cp_wait1();
        __syncthreads();
        if (kt < KITERS - 2) { issue((kt + 2) % NSTG, (kt + 2) * BKC); cp_commit(); }

        char* st = smem + (kt % NSTG) * STAGE_B;
        const uint32_t aH = smem_u32(st);
        const uint32_t aL = aH + PLANE_B;
        const uint32_t bH = aH + 2 * PLANE_B;
        const uint32_t bL = aH + 3 * PLANE_B;

#pragma unroll
        for (int ks = 0; ks < 2; ks++) {
            const int akc = ks * 16 + a_k8;
            const int bkc = ks * 16 + b_k8;
            uint32_t ah[4][4], al[4][4], bh[4][2], bl[4][2];
#pragma unroll
            for (int mf = 0; mf < 4; mf++) {
                const uint32_t off = ((a_row + mf * 16) * ROWP + akc) * 2;
                ldsm4(ah[mf], aH + off);
                ldsm4(al[mf], aL + off);
            }
#pragma unroll
            for (int p = 0; p < 2; p++) {
                const uint32_t off = ((b_row + p * 16) * ROWP + bkc) * 2;
                uint32_t t[4];
                ldsm4(t, bH + off);
                bh[p * 2][0] = t[0]; bh[p * 2][1] = t[1];
                bh[p * 2 + 1][0] = t[2]; bh[p * 2 + 1][1] = t[3];
                ldsm4(t, bL + off);
                bl[p * 2][0] = t[0]; bl[p * 2][1] = t[1];
                bl[p * 2 + 1][0] = t[2]; bl[p * 2 + 1][1] = t[3];
            }
#pragma unroll
            for (int mf = 0; mf < 4; mf++)
#pragma unroll
                for (int nf = 0; nf < 4; nf++) {
                    mma16816(acc[mf][nf], ah[mf], bh[nf]);
                    mma16816(acc[mf][nf], ah[mf], bl[nf]);
                    mma16816(acc[mf][nf], al[mf], bh[nf]);
                }
        }
        __syncthreads();
    }

    const int er = lane >> 2;
    const int ec = (lane & 3) * 2;
#pragma unroll
    for (int mf = 0; mf < 4; mf++) {
        const int m0 = bm + wm * 64 + mf * 16 + er;
#pragma unroll
        for (int nf = 0; nf < 4; nf++) {
            const int n0 = bn + wn * 32 + nf * 8 + ec;
            const float b0 = __ldg(&bias[n0]), b1 = __ldg(&bias[n0 + 1]);
            const float v00 = acc[mf][nf][0] + b0, v01 = acc[mf][nf][1] + b1;
            const float v10 = acc[mf][nf][2] + b0, v11 = acc[mf][nf][3] + b1;
            if (OUTF32) {
                *(float2*)(C + (size_t)m0 * N + n0)       = make_float2(v00, v01);
                *(float2*)(C + (size_t)(m0 + 8) * N + n0) = make_float2(v10, v11);
            } else {
                __nv_bfloat16 h0, h1, l0, l1;
                split1(v00, h0, l0); split1(v01, h1, l1);
                *(uint32_t*)(CH + (size_t)m0 * N + n0) = packbf(h0, h1);
                *(uint32_t*)(CL + (size_t)m0 * N + n0) = packbf(l0, l1);
                split1(v10, h0, l0); split1(v11, h1, l1);
                *(uint32_t*)(CH + (size_t)(m0 + 8) * N + n0) = packbf(h0, h1);
                *(uint32_t*)(CL + (size_t)(m0 + 8) * N + n0) = packbf(l0, l1);
            }
        }
    }
}

// ---------------------------------------------------------------------------
// Tensor-core window attention. Block = (b, h, q-half): 8 warps x 16 q rows.
// Flash online softmax over 4 key tiles of 64. Hi/lo split everywhere (1e-5).
// ---------------------------------------------------------------------------
__global__ __launch_bounds__(256, 1) void attn_tc(
    const __nv_bfloat16* __restrict__ Ph, const __nv_bfloat16* __restrict__ Pl,
    const float* __restrict__ biasg,
    __nv_bfloat16* __restrict__ ch, __nv_bfloat16* __restrict__ cl)
{
    const int bx = blockIdx.x;
    const int half = bx & 1, h = (bx >> 1) & 15, b = bx >> 5;
    const int tid = threadIdx.x, wid = tid >> 5, lane = tid & 31;
    const int gr = lane >> 2, nc = (lane & 3) * 2;
    const float L2E = 1.44269504f;

    __shared__ __nv_bfloat16 kh[64][ROWP2], kl[64][ROWP2];
    __shared__ __nv_bfloat16 vth[64][ROWP2], vtl[64][ROWP2];

    const int q0 = half * 128 + wid * 16;
    const size_t tok0 = (size_t)b * SEQ;

    // Q fragments straight from gmem planes (m16k16 layout)
    uint32_t qhf[4][4], qlf[4][4];
#pragma unroll
    for (int ks = 0; ks < 4; ks++)
#pragma unroll
        for (int r = 0; r < 4; r++) {
            const int row = q0 + gr + (r & 1) * 8;
            const int kk = ks * 16 + (r >> 1) * 8 + nc;
            const size_t off = (tok0 + row) * NQKV + h * HDIM + kk;
            qhf[ks][r] = *(const uint32_t*)(Ph + off);
            qlf[ks][r] = *(const uint32_t*)(Pl + off);
        }

    float oacc[8][4];
#pragma unroll
    for (int i = 0; i < 8; i++)
#pragma unroll
        for (int c = 0; c < 4; c++) oacc[i][c] = 0.f;
    float m0 = -1e30f, m1 = -1e30f, l0 = 0.f, l1 = 0.f;

    const uint32_t khB = smem_u32(kh), klB = smem_u32(kl);
    const uint32_t vhB = smem_u32(vth), vlB = smem_u32(vtl);
    const int brow_c = ((lane >> 4) << 3) + (lane & 7);
    const int bk8    = ((lane >> 3) & 1) * 8;

    for (int kt = 0; kt < 4; kt++) {
        __syncthreads();
        // K tile [key][d] (bf16 copy)
#pragma unroll
        for (int ps = 0; ps < 2; ps++) {
            const int idx = ps * 256 + tid;
            const int ky = idx >> 3, c8 = (idx & 7) * 8;
            const size_t off = (tok0 + kt * 64 + ky) * NQKV + EMB + h * HDIM + c8;
            *(uint4*)&kh[ky][c8] = *(const uint4*)(Ph + off);
            *(uint4*)&kl[ky][c8] = *(const uint4*)(Pl + off);
        }
        // V tile transposed: vt[d][key]
#pragma unroll
        for (int ps = 0; ps < 2; ps++) {
            const int idx = ps * 256 + tid;
            const int key = idx & 63, dg = idx >> 6;
            const size_t off = (tok0 + kt * 64 + key) * NQKV + 2 * EMB + h * HDIM + dg * 8;
            uint4 vh4 = *(const uint4*)(Ph + off);
            uint4 vl4 = *(const uint4*)(Pl + off);
            const __nv_bfloat16* ph = (const __nv_bfloat16*)&vh4;
            const __nv_bfloat16* pl = (const __nv_bfloat16*)&vl4;
#pragma unroll
            for (int j = 0; j < 8; j++) {
                vth[dg * 8 + j][key] = ph[j];
                vtl[dg * 8 + j][key] = pl[j];
            }
        }
        __syncthreads();

        // S = Q . K^T (hi/lo, 3 products)
        float s[8][4];
#pragma unroll
        for (int i = 0; i < 8; i++)
#pragma unroll
            for (int c = 0; c < 4; c++) s[i][c] = 0.f;

#pragma unroll
        for (int ks = 0; ks < 4; ks++) {
            uint32_t bh[8][2], bl[8][2];
#pragma unroll
            for (int nf2 = 0; nf2 < 4; nf2++) {
                const uint32_t boff = ((nf2 * 16 + brow_c) * ROWP2 + ks * 16 + bk8) * 2;
                uint32_t t[4];
                ldsm4(t, khB + boff);
                bh[nf2 * 2][0] = t[0]; bh[nf2 * 2][1] = t[1];
                bh[nf2 * 2 + 1][0] = t[2]; bh[nf2 * 2 + 1][1] = t[3];
                ldsm4(t, klB + boff);
                bl[nf2 * 2][0] = t[0]; bl[nf2 * 2][1] = t[1];
                bl[nf2 * 2 + 1][0] = t[2]; bl[nf2 * 2 + 1][1] = t[3];
            }
#pragma unroll
            for (int nf = 0; nf < 8; nf++) {
                mma16816(s[nf], qhf[ks], bh[nf]);
                mma16816(s[nf], qhf[ks], bl[nf]);
                mma16816(s[nf], qlf[ks], bh[nf]);
            }
        }

        // scale + bias + flash softmax
        const float* bq = biasg + ((size_t)h * SEQ + (q0 + gr)) * SEQ + kt * 64;
        float mx0 = -1e30f, mx1 = -1e30f;
#pragma unroll
        for (int nf = 0; nf < 8; nf++) {
            const float2 b0 = *(const float2*)(bq + nf * 8 + nc);
            const float2 b1 = *(const float2*)(bq + 8 * SEQ + nf * 8 + nc);
            s[nf][0] = fmaf(s[nf][0], 0.125f, b0.x);
            s[nf][1] = fmaf(s[nf][1], 0.125f, b0.y);
            s[nf][2] = fmaf(s[nf][2], 0.125f, b1.x);
            s[nf][3] = fmaf(s[nf][3], 0.125f, b1.y);
            mx0 = fmaxf(mx0, fmaxf(s[nf][0], s[nf][1]));
            mx1 = fmaxf(mx1, fmaxf(s[nf][2], s[nf][3]));
        }
        mx0 = fmaxf(mx0, __shfl_xor_sync(~0u, mx0, 1));
        mx0 = fmaxf(mx0, __shfl_xor_sync(~0u, mx0, 2));
        mx1 = fmaxf(mx1, __shfl_xor_sync(~0u, mx1, 1));
        mx1 = fmaxf(mx1, __shfl_xor_sync(~0u, mx1, 2));
        const float m0n = fmaxf(m0, mx0), m1n = fmaxf(m1, mx1);
        const float c0 = ex2f((m0 - m0n) * L2E);
        const float c1 = ex2f((m1 - m1n) * L2E);
        l0 *= c0; l1 *= c1;
        float ps0 = 0.f, ps1 = 0.f;
#pragma unroll
        for (int nf = 0; nf < 8; nf++) {
            oacc[nf][0] *= c0; oacc[nf][1] *= c0;
            oacc[nf][2] *= c1; oacc[nf][3] *= c1;
            s[nf][0] = ex2f((s[nf][0] - m0n) * L2E);
            s[nf][1] = ex2f((s[nf][1] - m0n) * L2E);
            s[nf][2] = ex2f((s[nf][2] - m1n) * L2E);
            s[nf][3] = ex2f((s[nf][3] - m1n) * L2E);
            ps0 += s[nf][0] + s[nf][1];
            ps1 += s[nf][2] + s[nf][3];
        }
        l0 += ps0; l1 += ps1;
        m0 = m0n; m1 = m1n;

        // O += P . V  (P hi/lo re-split in registers)
#pragma unroll
        for (int kv = 0; kv < 4; kv++) {
            uint32_t pah[4], pal[4];
#pragma unroll
            for (int r = 0; r < 4; r++) {
                const float x0 = s[2 * kv + (r >> 1)][(r & 1) * 2 + 0];
                const float x1 = s[2 * kv + (r >> 1)][(r & 1) * 2 + 1];
                __nv_bfloat16 hh0, hh1, ll0, ll1;
                split1(x0, hh0, ll0); split1(x1, hh1, ll1);
                pah[r] = packbf(hh0, hh1);
                pal[r] = packbf(ll0, ll1);
            }
            uint32_t bvh[8][2], bvl[8][2];
#pragma unroll
            for (int nf2 = 0; nf2 < 4; nf2++) {
                const uint32_t boff = ((nf2 * 16 + brow_c) * ROWP2 + kv * 16 + bk8) * 2;
                uint32_t t[4];
                ldsm4(t, vhB + boff);
                bvh[nf2 * 2][0] = t[0]; bvh[nf2 * 2][1] = t[1];
                bvh[nf2 * 2 + 1][0] = t[2]; bvh[nf2 * 2 + 1][1] = t[3];
                ldsm4(t, vlB + boff);
                bvl[nf2 * 2][0] = t[0]; bvl[nf2 * 2][1] = t[1];
                bvl[nf2 * 2 + 1][0] = t[2]; bvl[nf2 * 2 + 1][1] = t[3];
            }
#pragma unroll
            for (int nf = 0; nf < 8; nf++) {
                mma16816(oacc[nf], pah, bvh[nf]);
                mma16816(oacc[nf], pah, bvl[nf]);
                mma16816(oacc[nf], pal, bvh[nf]);
            }
        }
    }

    // finalize: reduce l across quad, normalize, write hi/lo ctx planes
    l0 += __shfl_xor_sync(~0u, l0, 1); l0 += __shfl_xor_sync(~0u, l0, 2);
    l1 += __shfl_xor_sync(~0u, l1, 1); l1 += __shfl_xor_sync(~0u, l1, 2);
    const float il0 = 1.f / l0, il1 = 1.f / l1;
    const size_t o0 = (tok0 + q0 + gr) * EMB + h * HDIM;
    const size_t o1 = o0 + (size_t)8 * EMB;
#pragma unroll
    for (int nf = 0; nf < 8; nf++) {
        const int d = nf * 8 + nc;
        __nv_bfloat16 h0, h1, lo0, lo1;
        split1(oacc[nf][0] * il0, h0, lo0);
        split1(oacc[nf][1] * il0, h1, lo1);
        *(uint32_t*)(ch + o0 + d) = packbf(h0, h1);
        *(uint32_t*)(cl + o0 + d) = packbf(lo0, lo1);
        split1(oacc[nf][2] * il1, h0, lo0);
        split1(oacc[nf][3] * il1, h1, lo1);
        *(uint32_t*)(ch + o1 + d) = packbf(h0, h1);
        *(uint32_t*)(cl + o1 + d) = packbf(lo0, lo1);
    }
}

// ---------------------------------------------------------------------------
extern "C" void kernel_launch(void* const* d_in, const int* in_sizes, int n_in,
                              void* d_out, int out_size)
{
    const float* x          = (const float*)d_in[0];
    const float* qkv_w      = (const float*)d_in[1];
    const float* qkv_b      = (const float*)d_in[2];
    const float* out_w      = (const float*)d_in[3];
    const float* out_b      = (const float*)d_in[4];
    const float* bias_table = (const float*)d_in[5];
    const int*   rel_index  = (const int*)d_in[6];
    float* out = (float*)d_out;

    __nv_bfloat16 *qkvh, *qkvl, *xh, *xl, *ch, *cl, *wqh, *wql, *woh, *wol;
    float* biasg;
    cudaGetSymbolAddress((void**)&qkvh, g_qkvh);
    cudaGetSymbolAddress((void**)&qkvl, g_qkvl);
    cudaGetSymbolAddress((void**)&xh, g_xh);
    cudaGetSymbolAddress((void**)&xl, g_xl);
    cudaGetSymbolAddress((void**)&ch, g_ch);
    cudaGetSymbolAddress((void**)&cl, g_cl);
    cudaGetSymbolAddress((void**)&wqh, g_wqh);
    cudaGetSymbolAddress((void**)&wql, g_wql);
    cudaGetSymbolAddress((void**)&woh, g_woh);
    cudaGetSymbolAddress((void**)&wol, g_wol);
    cudaGetSymbolAddress((void**)&biasg, g_biasg);

    const int smem_bytes = NSTG * STAGE_B;   // 122880
    cudaFuncSetAttribute(gemm_mma<1>, cudaFuncAttributeMaxDynamicSharedMemorySize,
                         smem_bytes);
    cudaFuncSetAttribute(gemm_mma<0>, cudaFuncAttributeMaxDynamicSharedMemorySize,
                         smem_bytes);

    // 0) splits + bias precompute
    split_kernel<<<1184, 256>>>(x,     xh,  xl,  MTOT * EMB / 4);
    split_kernel<<<1184, 256>>>(qkv_w, wqh, wql, NQKV * EMB / 4);
    split_kernel<<<592,  256>>>(out_w, woh, wol, EMB * EMB / 4);
    bias_pre<<<SEQ * SEQ / 256, 256>>>(bias_table, rel_index, biasg);

    // 1) QKV projection -> bf16 hi/lo planes
    {
        dim3 grid(NQKV / BN, MTOT / BM);
        gemm_mma<0><<<grid, 256, smem_bytes>>>(xh, xl, wqh, wql, qkv_b,
                                               nullptr, qkvh, qkvl, NQKV);
    }
    // 2) Tensor-core windowed attention -> ctx hi/lo planes
    attn_tc<<<BATCH * HEADS * 2, 256>>>(qkvh, qkvl, biasg, ch, cl);
    // 3) Output projection -> fp32 out
    {
        dim3 grid(EMB / BN, MTOT / BM);
        gemm_mma<1><<<grid, 256, smem_bytes>>>(ch, cl, woh, wol, out_b,
                                               out, nullptr, nullptr, EMB);
    }
}